// round 1
// baseline (speedup 1.0000x reference)
#include <cuda_runtime.h>
#include <cuda_bf16.h>

#define NE      1600000
#define NN      100000
#define NF      48
#define EFEAT   16
#define TOT     112      // 2*NF + EFEAT
#define HID     128
#define TILE_E  64
#define NTILES  (NE / TILE_E)   // 25000 exactly
#define NTH     256

// -------- scratch (device globals: allocation-free) --------
__device__ float g_msum[NN * NF];
__device__ float g_cnt[NN];
__device__ int   g_is64;

// -------- int64/int32 edge_index detection --------
// JAX with x64 disabled silently truncates the requested int64 to int32.
// If the array is really int64, every high 32-bit word is 0 (values < 1e5).
__global__ void detect_kernel(const int* __restrict__ ei) {
    if (threadIdx.x == 0) {
        int nz = 0;
        #pragma unroll
        for (int i = 0; i < 64; i++) nz += (ei[2 * i + 1] != 0);
        g_is64 = (nz == 0) ? 1 : 0;
    }
}

__device__ __forceinline__ int load_index(const int* __restrict__ ei, long long pos, int is64) {
    if (is64) return (int)(((const long long*)ei)[pos]);
    return ei[pos];
}

// -------- per-target edge counts --------
__global__ void count_kernel(const int* __restrict__ ei) {
    int is64 = g_is64;
    long long stride = (long long)gridDim.x * blockDim.x;
    for (long long e = (long long)blockIdx.x * blockDim.x + threadIdx.x; e < NE; e += stride) {
        int t = load_index(ei, (long long)NE + e, is64);
        atomicAdd(&g_cnt[t], 1.0f);
    }
}

// -------- fused gather + 3-layer MLP + scatter-add --------
// SMEM layout (floats):
//   sW1 [112][128] = 14336
//   sW2 [128][128] = 16384
//   sW3 [128][48]  =  6144
//   sA  [64][128]  =  8192   (layer-1 input; reused as H2)
//   sH1 [64][128]  =  8192
//   sb1 128, sb2 128, sb3 48
//   sIdx 128 ints  (src 64, tgt 64)
#define OFF_W1  0
#define OFF_W2  (OFF_W1 + TOT * HID)
#define OFF_W3  (OFF_W2 + HID * HID)
#define OFF_A   (OFF_W3 + HID * NF)
#define OFF_H1  (OFF_A + TILE_E * HID)
#define OFF_B1  (OFF_H1 + TILE_E * HID)
#define OFF_B2  (OFF_B1 + HID)
#define OFF_B3  (OFF_B2 + HID)
#define OFF_IDX (OFF_B3 + NF)
#define SMEM_FLOATS (OFF_IDX + 2 * TILE_E)
#define SMEM_BYTES  (SMEM_FLOATS * 4)

extern "C" __global__ void __launch_bounds__(NTH)
mlp_kernel(const float* __restrict__ x,
           const int*   __restrict__ ei,
           const float* __restrict__ ef,
           const float* __restrict__ W1, const float* __restrict__ b1,
           const float* __restrict__ W2, const float* __restrict__ b2,
           const float* __restrict__ W3, const float* __restrict__ b3)
{
    extern __shared__ float sm[];
    float* sW1 = sm + OFF_W1;
    float* sW2 = sm + OFF_W2;
    float* sW3 = sm + OFF_W3;
    float* sA  = sm + OFF_A;
    float* sH1 = sm + OFF_H1;
    float* sb1 = sm + OFF_B1;
    float* sb2 = sm + OFF_B2;
    float* sb3 = sm + OFF_B3;
    int*   sSrc = (int*)(sm + OFF_IDX);
    int*   sTgt = sSrc + TILE_E;

    const int tid = threadIdx.x;

    // ---- load weights once (persistent CTA) ----
    for (int i = tid; i < TOT * HID; i += NTH) sW1[i] = W1[i];
    for (int i = tid; i < HID * HID; i += NTH) sW2[i] = W2[i];
    for (int i = tid; i < HID * NF;  i += NTH) sW3[i] = W3[i];
    if (tid < HID) sb1[tid] = b1[tid];
    if (tid < HID) sb2[tid] = b2[tid];
    if (tid < NF)  sb3[tid] = b3[tid];
    const int is64 = g_is64;
    __syncthreads();

    const int w = tid >> 5;   // warp id: edge rows [w*8, w*8+8)
    const int l = tid & 31;   // lane:    hidden cols [l*4, l*4+4)
    const int e3   = tid >> 2;        // layer3: edge per 4 threads
    const int sub3 = tid & 3;         // layer3: feature group
    const int f0   = sub3 * 12;

    for (int T = blockIdx.x; T < NTILES; T += gridDim.x) {
        const long long eBase = (long long)T * TILE_E;

        if (tid < TILE_E) {
            sSrc[tid] = load_index(ei, eBase + tid, is64);
            sTgt[tid] = load_index(ei, (long long)NE + eBase + tid, is64);
        }
        __syncthreads();

        // ---- gather: edge matrix [64][112] as float4 chunks ----
        for (int i = tid; i < TILE_E * 28; i += NTH) {
            int e = i / 28, j = i % 28;
            float4 v; int col;
            if (j < 12)      { v = ((const float4*)(x + (long long)sSrc[e] * NF))[j];      col = j * 4; }
            else if (j < 24) { v = ((const float4*)(x + (long long)sTgt[e] * NF))[j - 12]; col = 48 + (j - 12) * 4; }
            else             { v = ((const float4*)(ef + (eBase + e) * EFEAT))[j - 24];    col = 96 + (j - 24) * 4; }
            *((float4*)&sA[e * HID + col]) = v;
        }
        __syncthreads();

        // ---- layer 1: H1 = relu(A @ W1 + b1), K = 112 ----
        {
            float acc[8][4];
            #pragma unroll
            for (int i = 0; i < 8; i++)
                #pragma unroll
                for (int j = 0; j < 4; j++) acc[i][j] = 0.f;
            #pragma unroll 4
            for (int k = 0; k < TOT; k++) {
                float4 wv = *((const float4*)&sW1[k * HID + l * 4]);
                #pragma unroll
                for (int i = 0; i < 8; i++) {
                    float a = sA[(w * 8 + i) * HID + k];   // warp-broadcast
                    acc[i][0] += a * wv.x; acc[i][1] += a * wv.y;
                    acc[i][2] += a * wv.z; acc[i][3] += a * wv.w;
                }
            }
            float4 bv = *((const float4*)&sb1[l * 4]);
            #pragma unroll
            for (int i = 0; i < 8; i++) {
                float4 r;
                r.x = fmaxf(acc[i][0] + bv.x, 0.f);
                r.y = fmaxf(acc[i][1] + bv.y, 0.f);
                r.z = fmaxf(acc[i][2] + bv.z, 0.f);
                r.w = fmaxf(acc[i][3] + bv.w, 0.f);
                *((float4*)&sH1[(w * 8 + i) * HID + l * 4]) = r;
            }
        }
        __syncthreads();

        // ---- layer 2: H2 = relu(H1 @ W2 + b2), K = 128 (H2 into sA region) ----
        {
            float acc[8][4];
            #pragma unroll
            for (int i = 0; i < 8; i++)
                #pragma unroll
                for (int j = 0; j < 4; j++) acc[i][j] = 0.f;
            #pragma unroll 4
            for (int k = 0; k < HID; k++) {
                float4 wv = *((const float4*)&sW2[k * HID + l * 4]);
                #pragma unroll
                for (int i = 0; i < 8; i++) {
                    float a = sH1[(w * 8 + i) * HID + k];
                    acc[i][0] += a * wv.x; acc[i][1] += a * wv.y;
                    acc[i][2] += a * wv.z; acc[i][3] += a * wv.w;
                }
            }
            float4 bv = *((const float4*)&sb2[l * 4]);
            #pragma unroll
            for (int i = 0; i < 8; i++) {
                float4 r;
                r.x = fmaxf(acc[i][0] + bv.x, 0.f);
                r.y = fmaxf(acc[i][1] + bv.y, 0.f);
                r.z = fmaxf(acc[i][2] + bv.z, 0.f);
                r.w = fmaxf(acc[i][3] + bv.w, 0.f);
                *((float4*)&sA[(w * 8 + i) * HID + l * 4]) = r;
            }
        }
        __syncthreads();

        // ---- layer 3: message = H2 @ W3 + b3, scatter-add, K = 128, N = 48 ----
        {
            float acc[12];
            #pragma unroll
            for (int j = 0; j < 12; j++) acc[j] = 0.f;
            #pragma unroll 2
            for (int k = 0; k < HID; k++) {
                float a = sA[e3 * HID + k];
                #pragma unroll
                for (int j = 0; j < 12; j++)
                    acc[j] += a * sW3[k * NF + f0 + j];
            }
            const int tgt = sTgt[e3];
            float* dst = g_msum + (long long)tgt * NF + f0;
            #pragma unroll
            for (int j = 0; j < 12; j++)
                atomicAdd(&dst[j], acc[j] + sb3[f0 + j]);
        }
        __syncthreads();   // protect sA/sIdx before next tile
    }
}

// -------- finalize: out = x + msum / max(cnt, 1) --------
__global__ void finalize_kernel(const float* __restrict__ x, float* __restrict__ out) {
    int i = blockIdx.x * blockDim.x + threadIdx.x;
    if (i < NN * NF) {
        float c = g_cnt[i / NF];
        out[i] = x[i] + g_msum[i] / fmaxf(c, 1.0f);
    }
}

extern "C" void kernel_launch(void* const* d_in, const int* in_sizes, int n_in,
                              void* d_out, int out_size) {
    const float* x  = (const float*)d_in[0];
    const int*   ei = (const int*)d_in[1];
    const float* ef = (const float*)d_in[2];
    const float* W1 = (const float*)d_in[3];
    const float* b1 = (const float*)d_in[4];
    const float* W2 = (const float*)d_in[5];
    const float* b2 = (const float*)d_in[6];
    const float* W3 = (const float*)d_in[7];
    const float* b3 = (const float*)d_in[8];
    float* out = (float*)d_out;

    void* pmsum = nullptr; void* pcnt = nullptr;
    cudaGetSymbolAddress(&pmsum, g_msum);
    cudaGetSymbolAddress(&pcnt, g_cnt);
    cudaMemsetAsync(pmsum, 0, sizeof(float) * NN * NF);
    cudaMemsetAsync(pcnt,  0, sizeof(float) * NN);

    detect_kernel<<<1, 32>>>(ei);
    count_kernel<<<1024, 256>>>(ei);

    cudaFuncSetAttribute(mlp_kernel, cudaFuncAttributeMaxDynamicSharedMemorySize, SMEM_BYTES);
    int nsm = 148;
    cudaDeviceGetAttribute(&nsm, cudaDevAttrMultiProcessorCount, 0);
    mlp_kernel<<<nsm, NTH, SMEM_BYTES>>>(x, ei, ef, W1, b1, W2, b2, W3, b3);

    finalize_kernel<<<(NN * NF + 255) / 256, 256>>>(x, out);
}

// round 7
// speedup vs baseline: 3.2242x; 3.2242x over previous
#include <cuda_runtime.h>
#include <cstdint>

#define NE      1600000
#define NN      100000
#define NF      48
#define EFEAT   16
#define TOT     112
#define HID     128
#define TILE_M  128
#define NTILES  (NE / TILE_M)   // 12500
#define NTH     256

#define SA   132   // activation stride (floats), %32==4 -> conflict-free A frags
#define SW   136   // weight stride (floats),     %32==8 -> conflict-free B frags
#define SW3  56    // W3 stride (>=48; %32==24 -> 24*tig+gid distinct -> conflict-free)

// SMEM float offsets
#define OFF_W1   0
#define OFF_W2   (OFF_W1 + TOT * SW)        // 112*136 = 15232
#define OFF_W3   (OFF_W2 + HID * SW)        // +128*136 = 32640
#define OFF_ACT  (OFF_W3 + HID * SW3)       // +128*56  = 39808
#define OFF_B1   (OFF_ACT + TILE_M * SA)    // +128*132 = 56704
#define OFF_B2   (OFF_B1 + HID)
#define OFF_B3   (OFF_B2 + HID)
#define OFF_SRC  (OFF_B3 + NF)
#define OFF_TGT  (OFF_SRC + TILE_M)
#define SMEM_FLOATS (OFF_TGT + TILE_M)
#define SMEM_BYTES  (SMEM_FLOATS * 4)       // 229,056 B <= 227 KB cap

__device__ float g_msum[NN * NF];
__device__ float g_cnt[NN];
__device__ int   g_is64;

__device__ __forceinline__ uint32_t f2tf(float f) {
    uint32_t u;
    asm("cvt.rna.tf32.f32 %0, %1;" : "=r"(u) : "f"(f));
    return u;
}

__device__ __forceinline__ void mma8(float* d, uint32_t a0, uint32_t a1,
                                     uint32_t a2, uint32_t a3,
                                     uint32_t b0, uint32_t b1) {
    asm("mma.sync.aligned.m16n8k8.row.col.f32.tf32.tf32.f32 "
        "{%0,%1,%2,%3}, {%4,%5,%6,%7}, {%8,%9}, {%0,%1,%2,%3};"
        : "+f"(d[0]), "+f"(d[1]), "+f"(d[2]), "+f"(d[3])
        : "r"(a0), "r"(a1), "r"(a2), "r"(a3), "r"(b0), "r"(b1));
}

// ---------------- small kernels ----------------
__global__ void detect_kernel(const int* __restrict__ ei) {
    if (threadIdx.x == 0) {
        int nz = 0;
        #pragma unroll 8
        for (int i = 0; i < 64; i++) nz += (ei[2 * i + 1] != 0);
        g_is64 = (nz == 0) ? 1 : 0;
    }
}
__device__ __forceinline__ int load_index(const int* __restrict__ ei, long long pos, int is64) {
    if (is64) return (int)(((const long long*)ei)[pos]);
    return ei[pos];
}
__global__ void count_kernel(const int* __restrict__ ei) {
    int is64 = g_is64;
    long long stride = (long long)gridDim.x * blockDim.x;
    for (long long e = (long long)blockIdx.x * blockDim.x + threadIdx.x; e < NE; e += stride) {
        int t = load_index(ei, (long long)NE + e, is64);
        atomicAdd(&g_cnt[t], 1.0f);
    }
}
__global__ void finalize_kernel(const float* __restrict__ x, float* __restrict__ out) {
    int i = blockIdx.x * blockDim.x + threadIdx.x;   // float4 index
    if (i < NN * NF / 4) {
        float c = fmaxf(g_cnt[i / 12], 1.0f);
        float4 m = ((const float4*)g_msum)[i];
        float4 xv = ((const float4*)x)[i];
        float4 o;
        o.x = xv.x + m.x / c; o.y = xv.y + m.y / c;
        o.z = xv.z + m.z / c; o.w = xv.w + m.w / c;
        ((float4*)out)[i] = o;
    }
}

// ---------------- main fused kernel ----------------
extern "C" __global__ void __launch_bounds__(NTH, 1)
mlp_mma_kernel(const float* __restrict__ x,
               const int*   __restrict__ ei,
               const float* __restrict__ ef,
               const float* __restrict__ W1, const float* __restrict__ b1,
               const float* __restrict__ W2, const float* __restrict__ b2,
               const float* __restrict__ W3, const float* __restrict__ b3)
{
    extern __shared__ float sm[];
    uint32_t* w1b = (uint32_t*)(sm + OFF_W1);
    uint32_t* w2b = (uint32_t*)(sm + OFF_W2);
    uint32_t* w3b = (uint32_t*)(sm + OFF_W3);
    float*    act = sm + OFF_ACT;
    uint32_t* actb = (uint32_t*)act;
    float* sb1 = sm + OFF_B1;
    float* sb2 = sm + OFF_B2;
    float* sb3 = sm + OFF_B3;
    int* sSrc = (int*)(sm + OFF_SRC);
    int* sTgt = (int*)(sm + OFF_TGT);

    const int tid = threadIdx.x;
    const int w = tid >> 5, lane = tid & 31;
    const int gid = lane >> 2, tig = lane & 3;
    const int row0 = w * 16 + gid;          // warp-private rows [16w,16w+16)
    const int row1 = row0 + 8;

    // ---- load + tf32-convert weights once ----
    for (int i = tid; i < TOT * HID; i += NTH) {
        int k = i >> 7, n = i & 127;
        w1b[k * SW + n] = f2tf(W1[i]);
    }
    for (int i = tid; i < HID * HID; i += NTH) {
        int k = i >> 7, n = i & 127;
        w2b[k * SW + n] = f2tf(W2[i]);
    }
    for (int i = tid; i < HID * NF; i += NTH) {
        int k = i / NF, n = i - k * NF;
        w3b[k * SW3 + n] = f2tf(W3[i]);
    }
    if (tid < HID) { sb1[tid] = b1[tid]; sb2[tid] = b2[tid]; }
    if (tid < NF)  sb3[tid] = b3[tid];
    const int is64 = g_is64;
    __syncthreads();

    for (int T = blockIdx.x; T < NTILES; T += gridDim.x) {
        const long long eBase = (long long)T * TILE_M;
        if (tid < TILE_M) {
            sSrc[tid] = load_index(ei, eBase + tid, is64);
            sTgt[tid] = load_index(ei, (long long)NE + eBase + tid, is64);
        }
        __syncthreads();

        // ---- gather: A[e][0:112] (tf32-rounded) ----
        for (int i = tid; i < TILE_M * 28; i += NTH) {
            int e = i / 28, j = i - e * 28;
            float4 v; int col;
            if (j < 12)      { v = ((const float4*)(x + (size_t)sSrc[e] * NF))[j];       col = j << 2; }
            else if (j < 24) { v = ((const float4*)(x + (size_t)sTgt[e] * NF))[j - 12];  col = 48 + ((j - 12) << 2); }
            else             { v = ((const float4*)(ef + (size_t)(eBase + e) * EFEAT))[j - 24]; col = 96 + ((j - 24) << 2); }
            uint4 t;
            t.x = f2tf(v.x); t.y = f2tf(v.y); t.z = f2tf(v.z); t.w = f2tf(v.w);
            *(uint4*)&actb[e * SA + col] = t;
        }
        __syncthreads();

        // ======== layer 1: H1 = relu(A @ W1 + b1), K=112, N=128 ========
        {
            float acc[16][4];
            #pragma unroll
            for (int n = 0; n < 16; n++) { acc[n][0]=0.f; acc[n][1]=0.f; acc[n][2]=0.f; acc[n][3]=0.f; }
            #pragma unroll
            for (int k = 0; k < 14; k++) {
                int kc = k * 8 + tig;
                uint32_t a0 = actb[row0 * SA + kc];
                uint32_t a1 = actb[row1 * SA + kc];
                uint32_t a2 = actb[row0 * SA + kc + 4];
                uint32_t a3 = actb[row1 * SA + kc + 4];
                const uint32_t* bp = w1b + kc * SW + gid;
                #pragma unroll
                for (int n = 0; n < 16; n++)
                    mma8(acc[n], a0, a1, a2, a3, bp[8 * n], bp[4 * SW + 8 * n]);
            }
            // epilogue (warp-local rows -> no barrier needed)
            #pragma unroll
            for (int n = 0; n < 16; n++) {
                int c = 8 * n + 2 * tig;
                uint2 u0, u1;
                u0.x = f2tf(fmaxf(acc[n][0] + sb1[c], 0.f));
                u0.y = f2tf(fmaxf(acc[n][1] + sb1[c + 1], 0.f));
                u1.x = f2tf(fmaxf(acc[n][2] + sb1[c], 0.f));
                u1.y = f2tf(fmaxf(acc[n][3] + sb1[c + 1], 0.f));
                *(uint2*)&actb[row0 * SA + c] = u0;
                *(uint2*)&actb[row1 * SA + c] = u1;
            }
        }

        // ======== layer 2: H2 = relu(H1 @ W2 + b2), K=128, N=128 ========
        {
            float acc[16][4];
            #pragma unroll
            for (int n = 0; n < 16; n++) { acc[n][0]=0.f; acc[n][1]=0.f; acc[n][2]=0.f; acc[n][3]=0.f; }
            #pragma unroll
            for (int k = 0; k < 16; k++) {
                int kc = k * 8 + tig;
                uint32_t a0 = actb[row0 * SA + kc];
                uint32_t a1 = actb[row1 * SA + kc];
                uint32_t a2 = actb[row0 * SA + kc + 4];
                uint32_t a3 = actb[row1 * SA + kc + 4];
                const uint32_t* bp = w2b + kc * SW + gid;
                #pragma unroll
                for (int n = 0; n < 16; n++)
                    mma8(acc[n], a0, a1, a2, a3, bp[8 * n], bp[4 * SW + 8 * n]);
            }
            #pragma unroll
            for (int n = 0; n < 16; n++) {
                int c = 8 * n + 2 * tig;
                uint2 u0, u1;
                u0.x = f2tf(fmaxf(acc[n][0] + sb2[c], 0.f));
                u0.y = f2tf(fmaxf(acc[n][1] + sb2[c + 1], 0.f));
                u1.x = f2tf(fmaxf(acc[n][2] + sb2[c], 0.f));
                u1.y = f2tf(fmaxf(acc[n][3] + sb2[c + 1], 0.f));
                *(uint2*)&actb[row0 * SA + c] = u0;
                *(uint2*)&actb[row1 * SA + c] = u1;
            }
        }

        // ======== layer 3: msg = H2 @ W3 + b3, K=128, N=48; scatter ========
        {
            float acc[6][4];
            #pragma unroll
            for (int n = 0; n < 6; n++) { acc[n][0]=0.f; acc[n][1]=0.f; acc[n][2]=0.f; acc[n][3]=0.f; }
            #pragma unroll
            for (int k = 0; k < 16; k++) {
                int kc = k * 8 + tig;
                uint32_t a0 = actb[row0 * SA + kc];
                uint32_t a1 = actb[row1 * SA + kc];
                uint32_t a2 = actb[row0 * SA + kc + 4];
                uint32_t a3 = actb[row1 * SA + kc + 4];
                const uint32_t* bp = w3b + kc * SW3 + gid;
                #pragma unroll
                for (int n = 0; n < 6; n++)
                    mma8(acc[n], a0, a1, a2, a3, bp[8 * n], bp[4 * SW3 + 8 * n]);
            }
            const int tgt0 = sTgt[row0], tgt1 = sTgt[row1];
            float* d0 = g_msum + (size_t)tgt0 * NF;
            float* d1 = g_msum + (size_t)tgt1 * NF;
            #pragma unroll
            for (int n = 0; n < 6; n++) {
                int c = 8 * n + 2 * tig;
                atomicAdd(d0 + c,     acc[n][0] + sb3[c]);
                atomicAdd(d0 + c + 1, acc[n][1] + sb3[c + 1]);
                atomicAdd(d1 + c,     acc[n][2] + sb3[c]);
                atomicAdd(d1 + c + 1, acc[n][3] + sb3[c + 1]);
            }
        }
        __syncthreads();   // all warps done reading act/sTgt before next tile's gather
    }
}

extern "C" void kernel_launch(void* const* d_in, const int* in_sizes, int n_in,
                              void* d_out, int out_size) {
    const float* x  = (const float*)d_in[0];
    const int*   ei = (const int*)d_in[1];
    const float* ef = (const float*)d_in[2];
    const float* W1 = (const float*)d_in[3];
    const float* b1 = (const float*)d_in[4];
    const float* W2 = (const float*)d_in[5];
    const float* b2 = (const float*)d_in[6];
    const float* W3 = (const float*)d_in[7];
    const float* b3 = (const float*)d_in[8];
    float* out = (float*)d_out;

    void* pmsum = nullptr; void* pcnt = nullptr;
    cudaGetSymbolAddress(&pmsum, g_msum);
    cudaGetSymbolAddress(&pcnt, g_cnt);
    cudaMemsetAsync(pmsum, 0, sizeof(float) * NN * NF);
    cudaMemsetAsync(pcnt,  0, sizeof(float) * NN);

    detect_kernel<<<1, 32>>>(ei);
    count_kernel<<<1024, 256>>>(ei);

    cudaFuncSetAttribute(mlp_mma_kernel, cudaFuncAttributeMaxDynamicSharedMemorySize, SMEM_BYTES);
    int nsm = 148;
    cudaDeviceGetAttribute(&nsm, cudaDevAttrMultiProcessorCount, 0);
    mlp_mma_kernel<<<nsm, NTH, SMEM_BYTES>>>(x, ei, ef, W1, b1, W2, b2, W3, b3);

    finalize_kernel<<<(NN * NF / 4 + 255) / 256, 256>>>(x, out);
}